// round 13
// baseline (speedup 1.0000x reference)
#include <cuda_runtime.h>

#define DIM 128
#define N 512
#define HEADS 4
#define DH 32
#define HID 128
#define IND 5
#define ATTN_SCALE 0.17677669529663687f   // 32^-0.5

// Scratch (allocation-free rule: __device__ globals). 256B-aligned (vector access).
__device__ __align__(256) float g_qkv[3 * HID * N];     // [384][512] q|k|v
__device__ __align__(256) float g_A2[HEADS * IND * N];  // [h][c][i]
__device__ __align__(256) float g_B3[HEADS * IND * N];  // [h][c][j]
__device__ __align__(256) float g_W4[HEADS * 25];       // [h][c*5+cp]
__device__ __align__(256) float g_qk[HEADS * N * N];    // [h][i][j] raw q.k

// ---------------------------------------------------------------------------
// K1: qkv = w_qkv (384x128) @ x (128x512). TM=32, TN=32, TK=128 (whole K
// staged once, ONE sync, no k-loop iterations). 256 threads, grid (16,12).
// Epilogue computes A2/B3 (per-head blocks) and W4.
// ---------------------------------------------------------------------------
__global__ __launch_bounds__(256) void k_qkv(const float* __restrict__ A,
                                             const float* __restrict__ B,
                                             const float* __restrict__ w_ind,
                                             float* __restrict__ C) {
    __shared__ float As[32][132];   // [m][k], pad 132 (16B-aligned rows)
    __shared__ float Bs[128][36];   // [k][n], pad 36  (16B-aligned rows)
    __shared__ float Cs[32][33];
    __shared__ float wsm[32][5];
    const int n0 = blockIdx.x * 32;
    const int m0 = blockIdx.y * 32;
    const int t  = threadIdx.x;
    const int tx = t & 15, ty = t >> 4;

    // ---- stage A tile: 32 rows x 128 cols, coalesced float4 ----
#pragma unroll
    for (int r = 0; r < 4; r++) {
        int idx = t + 256 * r;            // 0..1023
        int m = idx >> 5, k4 = idx & 31;  // warp = one full row
        float4 v = *(const float4*)(A + (m0 + m) * DIM + k4 * 4);
        *(float4*)&As[m][k4 * 4] = v;
    }
    // ---- stage B tile: 128 rows x 32 cols, coalesced float4 ----
#pragma unroll
    for (int r = 0; r < 4; r++) {
        int idx = t + 256 * r;            // 0..1023
        int kk = idx >> 3, n4 = idx & 7;
        float4 v = *(const float4*)(B + kk * N + n0 + n4 * 4);
        *(float4*)&Bs[kk][n4 * 4] = v;
    }
    __syncthreads();                      // the only sync before compute

    float acc00 = 0.f, acc01 = 0.f, acc10 = 0.f, acc11 = 0.f;
#pragma unroll 16
    for (int kk = 0; kk < DIM; kk++) {
        float a0 = As[2 * ty][kk];
        float a1 = As[2 * ty + 1][kk];
        float2 b = *(const float2*)&Bs[kk][2 * tx];
        acc00 = fmaf(a0, b.x, acc00);
        acc01 = fmaf(a0, b.y, acc01);
        acc10 = fmaf(a1, b.x, acc10);
        acc11 = fmaf(a1, b.y, acc11);
    }

    // write C and stage tile in smem for the epilogue
    {
        float* cp = &C[(m0 + 2 * ty) * N + n0 + tx * 2];
        cp[0] = acc00; cp[1] = acc01;
        Cs[2 * ty][tx * 2 + 0] = acc00;
        Cs[2 * ty][tx * 2 + 1] = acc01;
        cp = &C[(m0 + 2 * ty + 1) * N + n0 + tx * 2];
        cp[0] = acc10; cp[1] = acc11;
        Cs[2 * ty + 1][tx * 2 + 0] = acc10;
        Cs[2 * ty + 1][tx * 2 + 1] = acc11;
    }

    if (m0 < 2 * HID) {
        // A2 (q-blocks) / B3 (k-blocks): 32 cols x 5 coeffs, 32-deep dots
        const bool isQ = (m0 < HID);
        const int wbase = isQ ? (HID + m0) : (m0 - HID);   // wk rows for A2, wq rows for B3
        if (t < 160) wsm[t / 5][t % 5] = w_ind[(wbase + t / 5) * IND + (t % 5)];
        __syncthreads();
        const int h = (isQ ? m0 : m0 - HID) >> 5;
        float* dst = (isQ ? g_A2 : g_B3);
        if (t < 160) {
            int col = t & 31, c = t >> 5;
            float s = 0.f;
#pragma unroll
            for (int d = 0; d < DH; d++)
                s = fmaf(Cs[d][col], wsm[d][c], s);
            dst[(h * IND + c) * N + n0 + col] = s;
        }
    } else if (m0 == 2 * HID && n0 == 0) {
        if (t < HEADS * 25) {
            int h = t / 25, c = (t % 25) / 5, cp = t % 5;
            float s = 0.f;
#pragma unroll
            for (int d = 0; d < DH; d++)
                s = fmaf(w_ind[(h * DH + d) * IND + c],
                         w_ind[(HID + h * DH + d) * IND + cp], s);
            g_W4[t] = s;
        }
    }
}

// ---------------------------------------------------------------------------
// K2: g_qk[h][i][j] = sum_d q[h,d,i]*k[h,d,j].  64x64 tile, 4x4 rtile.
// ---------------------------------------------------------------------------
__global__ __launch_bounds__(256) void k_qk() {
    __shared__ float qs[DH][64];
    __shared__ float ks[DH][64];
    const int j0 = blockIdx.x * 64;
    const int i0 = blockIdx.y * 64;
    const int h  = blockIdx.z;
    const int t  = threadIdx.x;
    const int tx = t & 15, ty = t >> 4;

    const float* qb = g_qkv + (h * DH) * N;
    const float* kb = g_qkv + (HID + h * DH) * N;
#pragma unroll
    for (int idx = t; idx < DH * 16; idx += 256) {
        int d = idx >> 4, c4 = idx & 15;
        ((float4*)&qs[d][0])[c4] = ((const float4*)(qb + d * N + i0))[c4];
        ((float4*)&ks[d][0])[c4] = ((const float4*)(kb + d * N + j0))[c4];
    }
    __syncthreads();

    float acc[4][4] = {};
#pragma unroll
    for (int d = 0; d < DH; d++) {
        float4 qa = ((const float4*)&qs[d][0])[ty];
        float4 kv = ((const float4*)&ks[d][0])[tx];
        acc[0][0] = fmaf(qa.x, kv.x, acc[0][0]);
        acc[0][1] = fmaf(qa.x, kv.y, acc[0][1]);
        acc[0][2] = fmaf(qa.x, kv.z, acc[0][2]);
        acc[0][3] = fmaf(qa.x, kv.w, acc[0][3]);
        acc[1][0] = fmaf(qa.y, kv.x, acc[1][0]);
        acc[1][1] = fmaf(qa.y, kv.y, acc[1][1]);
        acc[1][2] = fmaf(qa.y, kv.z, acc[1][2]);
        acc[1][3] = fmaf(qa.y, kv.w, acc[1][3]);
        acc[2][0] = fmaf(qa.z, kv.x, acc[2][0]);
        acc[2][1] = fmaf(qa.z, kv.y, acc[2][1]);
        acc[2][2] = fmaf(qa.z, kv.z, acc[2][2]);
        acc[2][3] = fmaf(qa.z, kv.w, acc[2][3]);
        acc[3][0] = fmaf(qa.w, kv.x, acc[3][0]);
        acc[3][1] = fmaf(qa.w, kv.y, acc[3][1]);
        acc[3][2] = fmaf(qa.w, kv.z, acc[3][2]);
        acc[3][3] = fmaf(qa.w, kv.w, acc[3][3]);
    }
    float* cb = g_qk + ((size_t)h * N) * N;
#pragma unroll
    for (int r = 0; r < 4; r++) {
        int i = i0 + ty * 4 + r;
        ((float4*)&cb[(size_t)i * N + j0])[tx] =
            make_float4(acc[r][0], acc[r][1], acc[r][2], acc[r][3]);
    }
}

// ---------------------------------------------------------------------------
// K3: fused sim + softmax + attn@v + w_out projection.  FOUR i's per block,
// 512 threads (grid 128). Raw sims staged in smem; softmax as a
// warp-per-(i,h) smem pass. v streamed once per 4 i.
// ---------------------------------------------------------------------------
__global__ __launch_bounds__(512) void k_fused(const float* __restrict__ indicator,
                                               const float* __restrict__ w_out,
                                               const float* __restrict__ b_out,
                                               float* __restrict__ out) {
    const int i0 = blockIdx.x * 4;      // handles i0..i0+3
    const int t = threadIdx.x;          // Pass A: owns column j = t
    const int warp = t >> 5, lane = t & 31;

    __shared__ float a2s[4][HEADS][IND];
    __shared__ float w4s[HEADS][25];
    __shared__ float inv_s[4][HEADS];
    __shared__ __align__(16) float ps[4][HEADS][N];   // 32 KB: sims -> probs
    __shared__ __align__(16) float avs[4][HID];       // 2 KB

    if (t < 80) {
        int ii = t / 20, u = t % 20;
        a2s[ii][u / 5][u % 5] = g_A2[u * N + i0 + ii];
    } else if (t < 180) {
        int u = t - 80;
        w4s[u / 25][u % 25] = g_W4[u];
    }
    __syncthreads();

    // ---- Pass A: raw sims into smem ----
#pragma unroll
    for (int ii = 0; ii < 4; ii++) {
        float iv[IND];
#pragma unroll
        for (int c = 0; c < IND; c++)
            iv[c] = indicator[((size_t)c * N + i0 + ii) * N + t];
#pragma unroll
        for (int h = 0; h < HEADS; h++) {
            float qk = g_qk[((size_t)h * N + i0 + ii) * N + t];
            float lin = 0.f, quad = 0.f;
#pragma unroll
            for (int c = 0; c < IND; c++) {
                float b3 = g_B3[(h * IND + c) * N + t];
                lin = fmaf(iv[c], a2s[ii][h][c] + b3, lin);
                float tt = 0.f;
#pragma unroll
                for (int cp = 0; cp < IND; cp++)
                    tt = fmaf(w4s[h][c * 5 + cp], iv[cp], tt);
                quad = fmaf(iv[c], tt, quad);
            }
            ps[ii][h][t] = ATTN_SCALE * (qk + lin + quad);
        }
    }
    __syncthreads();

    // ---- softmax: one warp per (ii,h) pair over its 512 sims ----
    {
        const int ii = warp >> 2, h = warp & 3;
        float4* pr = (float4*)&ps[ii][h][0];
        float4 vals[4];
        float m = -1e30f;
#pragma unroll
        for (int k2 = 0; k2 < 4; k2++) {
            vals[k2] = pr[lane + 32 * k2];
            m = fmaxf(m, fmaxf(fmaxf(vals[k2].x, vals[k2].y),
                               fmaxf(vals[k2].z, vals[k2].w)));
        }
#pragma unroll
        for (int off = 16; off; off >>= 1)
            m = fmaxf(m, __shfl_xor_sync(0xffffffffu, m, off));
        float s = 0.f;
#pragma unroll
        for (int k2 = 0; k2 < 4; k2++) {
            vals[k2].x = __expf(vals[k2].x - m);
            vals[k2].y = __expf(vals[k2].y - m);
            vals[k2].z = __expf(vals[k2].z - m);
            vals[k2].w = __expf(vals[k2].w - m);
            s += (vals[k2].x + vals[k2].y) + (vals[k2].z + vals[k2].w);
            pr[lane + 32 * k2] = vals[k2];
        }
#pragma unroll
        for (int off = 16; off; off >>= 1)
            s += __shfl_xor_sync(0xffffffffu, s, off);
        if (lane == 0) inv_s[ii][h] = 1.0f / s;
    }
    __syncthreads();

    // ---- attn@v: v streamed once, 4 i's accumulated together ----
#pragma unroll
    for (int rr = 0; rr < 8; rr++) {
        int row = warp * 8 + rr;             // 0..127
        int h = row >> 5;
        const float4* vr = (const float4*)(g_qkv + (2 * HID + row) * N);
        float acc[4] = {};
#pragma unroll
        for (int k2 = 0; k2 < 4; k2++) {
            float4 v4 = vr[lane + 32 * k2];
#pragma unroll
            for (int ii = 0; ii < 4; ii++) {
                float4 p4 = ((const float4*)&ps[ii][h][0])[lane + 32 * k2];
                acc[ii] = fmaf(v4.x, p4.x, acc[ii]);
                acc[ii] = fmaf(v4.y, p4.y, acc[ii]);
                acc[ii] = fmaf(v4.z, p4.z, acc[ii]);
                acc[ii] = fmaf(v4.w, p4.w, acc[ii]);
            }
        }
#pragma unroll
        for (int off = 16; off; off >>= 1)
#pragma unroll
            for (int ii = 0; ii < 4; ii++)
                acc[ii] += __shfl_xor_sync(0xffffffffu, acc[ii], off);
        if (lane == 0)
#pragma unroll
            for (int ii = 0; ii < 4; ii++)
                avs[ii][row] = acc[ii] * inv_s[ii][h];
    }
    __syncthreads();

    // ---- projection for the 4 i's ----
#pragma unroll
    for (int rr = 0; rr < 8; rr++) {
        int o = warp * 8 + rr;               // 0..127
        float4 w4 = ((const float4*)(w_out + o * HID))[lane];
        float acc[4];
#pragma unroll
        for (int ii = 0; ii < 4; ii++) {
            float4 a4 = ((const float4*)&avs[ii][0])[lane];
            acc[ii] = w4.x * a4.x + w4.y * a4.y + w4.z * a4.z + w4.w * a4.w;
        }
#pragma unroll
        for (int off = 16; off; off >>= 1)
#pragma unroll
            for (int ii = 0; ii < 4; ii++)
                acc[ii] += __shfl_xor_sync(0xffffffffu, acc[ii], off);
        if (lane == 0) {
            float bv = b_out[o];
#pragma unroll
            for (int ii = 0; ii < 4; ii++)
                out[o * N + i0 + ii] = acc[ii] + bv;
        }
    }
}

// ---------------------------------------------------------------------------
extern "C" void kernel_launch(void* const* d_in, const int* in_sizes, int n_in,
                              void* d_out, int out_size) {
    const float* x         = (const float*)d_in[0];   // (1,128,512)
    const float* indicator = (const float*)d_in[1];   // (1,5,512,512)
    const float* w_qkv     = (const float*)d_in[2];   // (384,128)
    const float* w_ind     = (const float*)d_in[3];   // (256,5)
    const float* w_out     = (const float*)d_in[4];   // (128,128)
    const float* b_out     = (const float*)d_in[5];   // (128,)
    float* out             = (float*)d_out;           // (1,128,512)

    float* qkv;  cudaGetSymbolAddress((void**)&qkv, g_qkv);

    k_qkv<<<dim3(16, 12), 256>>>(w_qkv, x, w_ind, qkv);   // qkv + A2/B3/W4 (single-sync)
    k_qk<<<dim3(8, 8, 4), 256>>>();                        // raw q.k
    k_fused<<<N / 4, 512>>>(indicator, w_out, b_out, out); // sim+softmax+av+proj
}

// round 14
// speedup vs baseline: 1.4164x; 1.4164x over previous
#include <cuda_runtime.h>

#define DIM 128
#define N 512
#define HEADS 4
#define DH 32
#define HID 128
#define IND 5
#define ATTN_SCALE 0.17677669529663687f   // 32^-0.5

// Scratch (allocation-free rule: __device__ globals). 256B-aligned (vector access).
__device__ __align__(256) float g_qkv[3 * HID * N];     // [384][512] q|k|v
__device__ __align__(256) float g_A2[HEADS * IND * N];  // [h][c][i]
__device__ __align__(256) float g_B3[HEADS * IND * N];  // [h][c][j]
__device__ __align__(256) float g_W4[HEADS * 25];       // [h][c*5+cp]

// ---------------------------------------------------------------------------
// K1: qkv = w_qkv (384x128) @ x (128x512). TM=32, TN=32, TK=16, 256 threads,
// grid (16,12)=192 blocks. Register double-buffer; epilogue computes A2/B3/W4.
// (Round-10 version — the real 31.2us champion component.)
// ---------------------------------------------------------------------------
__global__ __launch_bounds__(256) void k_qkv(const float* __restrict__ A,
                                             const float* __restrict__ B,
                                             const float* __restrict__ w_ind,
                                             float* __restrict__ C) {
    __shared__ float As[16][32];
    __shared__ float Bs[16][32];
    __shared__ float Cs[32][33];
    __shared__ float wsm[32][5];
    const int n0 = blockIdx.x * 32;
    const int m0 = blockIdx.y * 32;
    const int t  = threadIdx.x;
    const int tx = t & 15, ty = t >> 4;

    const int a_k = t & 15, a_m = t >> 4;
    const int b_n = t & 31, b_k = t >> 5;

    As[a_k][a_m]      = A[(m0 + a_m) * DIM + a_k];
    As[a_k][a_m + 16] = A[(m0 + a_m + 16) * DIM + a_k];
    Bs[b_k][b_n]      = B[b_k * N + n0 + b_n];
    Bs[b_k + 8][b_n]  = B[(b_k + 8) * N + n0 + b_n];
    __syncthreads();

    float acc[2][2] = {};
    for (int k0 = 0; k0 < DIM; k0 += 16) {
        float ra0 = 0.f, ra1 = 0.f, rb0 = 0.f, rb1 = 0.f;
        const bool more = (k0 + 16 < DIM);
        if (more) {
            ra0 = A[(m0 + a_m) * DIM + k0 + 16 + a_k];
            ra1 = A[(m0 + a_m + 16) * DIM + k0 + 16 + a_k];
            rb0 = B[(k0 + 16 + b_k) * N + n0 + b_n];
            rb1 = B[(k0 + 24 + b_k) * N + n0 + b_n];
        }
#pragma unroll
        for (int kk = 0; kk < 16; kk++) {
            float2 a = ((const float2*)&As[kk][0])[ty];
            float2 b = ((const float2*)&Bs[kk][0])[tx];
            acc[0][0] = fmaf(a.x, b.x, acc[0][0]);
            acc[0][1] = fmaf(a.x, b.y, acc[0][1]);
            acc[1][0] = fmaf(a.y, b.x, acc[1][0]);
            acc[1][1] = fmaf(a.y, b.y, acc[1][1]);
        }
        __syncthreads();
        if (more) {
            As[a_k][a_m]      = ra0;
            As[a_k][a_m + 16] = ra1;
            Bs[b_k][b_n]      = rb0;
            Bs[b_k + 8][b_n]  = rb1;
            __syncthreads();
        }
    }
#pragma unroll
    for (int r = 0; r < 2; r++) {
        int m = ty * 2 + r;
        float* cp = &C[(m0 + m) * N + n0 + tx * 2];
        cp[0] = acc[r][0]; cp[1] = acc[r][1];
        Cs[m][tx * 2 + 0] = acc[r][0];
        Cs[m][tx * 2 + 1] = acc[r][1];
    }

    if (m0 < 2 * HID) {
        const bool isQ = (m0 < HID);
        const int wbase = isQ ? (HID + m0) : (m0 - HID);
        if (t < 160) wsm[t / 5][t % 5] = w_ind[(wbase + t / 5) * IND + (t % 5)];
        __syncthreads();
        const int h = (isQ ? m0 : m0 - HID) >> 5;
        float* dst = (isQ ? g_A2 : g_B3);
        if (t < 160) {
            int col = t & 31, c = t >> 5;
            float s = 0.f;
#pragma unroll
            for (int d = 0; d < DH; d++)
                s = fmaf(Cs[d][col], wsm[d][c], s);
            dst[(h * IND + c) * N + n0 + col] = s;
        }
    } else if (m0 == 2 * HID && n0 == 0) {
        if (t < HEADS * 25) {
            int h = t / 25, c = (t % 25) / 5, cp = t % 5;
            float s = 0.f;
#pragma unroll
            for (int d = 0; d < DH; d++)
                s = fmaf(w_ind[(h * DH + d) * IND + c],
                         w_ind[(HID + h * DH + d) * IND + cp], s);
            g_W4[t] = s;
        }
    }
}

// ---------------------------------------------------------------------------
// K2: fully fused qk + sim + softmax + attn@v + w_out projection.
// FOUR i's per block, 512 threads (grid 128). qk computed on the fly from
// a 2KB q-slice in smem; sims staged in smem; warp-per-(i,h) softmax;
// v streamed once per 4 i. g_qk is gone entirely.
// ---------------------------------------------------------------------------
__global__ __launch_bounds__(512) void k_fused(const float* __restrict__ indicator,
                                               const float* __restrict__ w_out,
                                               const float* __restrict__ b_out,
                                               float* __restrict__ out) {
    const int i0 = blockIdx.x * 4;      // handles i0..i0+3
    const int t = threadIdx.x;          // Pass A: owns column j = t
    const int warp = t >> 5, lane = t & 31;

    __shared__ float a2s[4][HEADS][IND];
    __shared__ float w4s[HEADS][25];
    __shared__ float inv_s[4][HEADS];
    __shared__ __align__(16) float qsm[HEADS][DH][4];  // q[h][d][ii], 2 KB
    __shared__ __align__(16) float ps[4][HEADS][N];    // 32 KB: sims -> probs
    __shared__ __align__(16) float avs[4][HID];        // 2 KB

    // q-slice: thread t -> (h, d, ii)
    {
        int h = t >> 7, rem = t & 127, d = rem >> 2, ii = rem & 3;
        qsm[h][d][ii] = g_qkv[(h * DH + d) * N + i0 + ii];
    }
    if (t < 80) {
        int ii = t / 20, u = t % 20;
        a2s[ii][u / 5][u % 5] = g_A2[u * N + i0 + ii];
    } else if (t < 180) {
        int u = t - 80;
        w4s[u / 25][u % 25] = g_W4[u];
    }
    __syncthreads();

    // ---- qk on the fly: qk[ii][h] = sum_d q[h,d,i0+ii] * k[h,d,t] ----
    float qk[4][HEADS] = {};
#pragma unroll
    for (int h = 0; h < HEADS; h++) {
#pragma unroll
        for (int d = 0; d < DH; d++) {
            float kv = g_qkv[(HID + h * DH + d) * N + t];
            float4 qv = *(const float4*)&qsm[h][d][0];
            qk[0][h] = fmaf(qv.x, kv, qk[0][h]);
            qk[1][h] = fmaf(qv.y, kv, qk[1][h]);
            qk[2][h] = fmaf(qv.z, kv, qk[2][h]);
            qk[3][h] = fmaf(qv.w, kv, qk[3][h]);
        }
    }

    // ---- Pass A: raw sims into smem ----
#pragma unroll
    for (int ii = 0; ii < 4; ii++) {
        float iv[IND];
#pragma unroll
        for (int c = 0; c < IND; c++)
            iv[c] = indicator[((size_t)c * N + i0 + ii) * N + t];
#pragma unroll
        for (int h = 0; h < HEADS; h++) {
            float lin = 0.f, quad = 0.f;
#pragma unroll
            for (int c = 0; c < IND; c++) {
                float b3 = g_B3[(h * IND + c) * N + t];
                lin = fmaf(iv[c], a2s[ii][h][c] + b3, lin);
                float tt = 0.f;
#pragma unroll
                for (int cp = 0; cp < IND; cp++)
                    tt = fmaf(w4s[h][c * 5 + cp], iv[cp], tt);
                quad = fmaf(iv[c], tt, quad);
            }
            ps[ii][h][t] = ATTN_SCALE * (qk[ii][h] + lin + quad);
        }
    }
    __syncthreads();

    // ---- softmax: one warp per (ii,h) pair over its 512 sims ----
    {
        const int ii = warp >> 2, h = warp & 3;
        float4* pr = (float4*)&ps[ii][h][0];
        float4 vals[4];
        float m = -1e30f;
#pragma unroll
        for (int k2 = 0; k2 < 4; k2++) {
            vals[k2] = pr[lane + 32 * k2];
            m = fmaxf(m, fmaxf(fmaxf(vals[k2].x, vals[k2].y),
                               fmaxf(vals[k2].z, vals[k2].w)));
        }
#pragma unroll
        for (int off = 16; off; off >>= 1)
            m = fmaxf(m, __shfl_xor_sync(0xffffffffu, m, off));
        float s = 0.f;
#pragma unroll
        for (int k2 = 0; k2 < 4; k2++) {
            vals[k2].x = __expf(vals[k2].x - m);
            vals[k2].y = __expf(vals[k2].y - m);
            vals[k2].z = __expf(vals[k2].z - m);
            vals[k2].w = __expf(vals[k2].w - m);
            s += (vals[k2].x + vals[k2].y) + (vals[k2].z + vals[k2].w);
            pr[lane + 32 * k2] = vals[k2];
        }
#pragma unroll
        for (int off = 16; off; off >>= 1)
            s += __shfl_xor_sync(0xffffffffu, s, off);
        if (lane == 0) inv_s[ii][h] = 1.0f / s;
    }
    __syncthreads();

    // ---- attn@v: v streamed once, 4 i's accumulated together ----
#pragma unroll
    for (int rr = 0; rr < 8; rr++) {
        int row = warp * 8 + rr;             // 0..127
        int h = row >> 5;
        const float4* vr = (const float4*)(g_qkv + (2 * HID + row) * N);
        float acc[4] = {};
#pragma unroll
        for (int k2 = 0; k2 < 4; k2++) {
            float4 v4 = vr[lane + 32 * k2];
#pragma unroll
            for (int ii = 0; ii < 4; ii++) {
                float4 p4 = ((const float4*)&ps[ii][h][0])[lane + 32 * k2];
                acc[ii] = fmaf(v4.x, p4.x, acc[ii]);
                acc[ii] = fmaf(v4.y, p4.y, acc[ii]);
                acc[ii] = fmaf(v4.z, p4.z, acc[ii]);
                acc[ii] = fmaf(v4.w, p4.w, acc[ii]);
            }
        }
#pragma unroll
        for (int off = 16; off; off >>= 1)
#pragma unroll
            for (int ii = 0; ii < 4; ii++)
                acc[ii] += __shfl_xor_sync(0xffffffffu, acc[ii], off);
        if (lane == 0)
#pragma unroll
            for (int ii = 0; ii < 4; ii++)
                avs[ii][row] = acc[ii] * inv_s[ii][h];
    }
    __syncthreads();

    // ---- projection for the 4 i's ----
#pragma unroll
    for (int rr = 0; rr < 8; rr++) {
        int o = warp * 8 + rr;               // 0..127
        float4 w4 = ((const float4*)(w_out + o * HID))[lane];
        float acc[4];
#pragma unroll
        for (int ii = 0; ii < 4; ii++) {
            float4 a4 = ((const float4*)&avs[ii][0])[lane];
            acc[ii] = w4.x * a4.x + w4.y * a4.y + w4.z * a4.z + w4.w * a4.w;
        }
#pragma unroll
        for (int off = 16; off; off >>= 1)
#pragma unroll
            for (int ii = 0; ii < 4; ii++)
                acc[ii] += __shfl_xor_sync(0xffffffffu, acc[ii], off);
        if (lane == 0) {
            float bv = b_out[o];
#pragma unroll
            for (int ii = 0; ii < 4; ii++)
                out[o * N + i0 + ii] = acc[ii] + bv;
        }
    }
}

// ---------------------------------------------------------------------------
extern "C" void kernel_launch(void* const* d_in, const int* in_sizes, int n_in,
                              void* d_out, int out_size) {
    const float* x         = (const float*)d_in[0];   // (1,128,512)
    const float* indicator = (const float*)d_in[1];   // (1,5,512,512)
    const float* w_qkv     = (const float*)d_in[2];   // (384,128)
    const float* w_ind     = (const float*)d_in[3];   // (256,5)
    const float* w_out     = (const float*)d_in[4];   // (128,128)
    const float* b_out     = (const float*)d_in[5];   // (128,)
    float* out             = (float*)d_out;           // (1,128,512)

    float* qkv;  cudaGetSymbolAddress((void**)&qkv, g_qkv);

    k_qkv<<<dim3(16, 12), 256>>>(w_qkv, x, w_ind, qkv);   // qkv + A2/B3/W4
    k_fused<<<N / 4, 512>>>(indicator, w_out, b_out, out); // qk+sim+softmax+av+proj
}